// round 15
// baseline (speedup 1.0000x reference)
#include <cuda_runtime.h>
#include <cuda_bf16.h>
#include <math.h>
#include <stdint.h>

// ---------------- problem constants ----------------
#define BB 4
#define SS 2048
#define INF_DIM 64
#define DD 128
#define HID 400
#define HH 4
#define KK 20
#define NSEL 32
#define NA 18

#define NTOK 8192          // B*S
#define NTOK2 16384        // 2*B*S (true + sim)
#define NROW 32768         // B*H*S
#define KOFF ((size_t)NTOK * (HH * DD))   // offset of k rows inside g_qk

// output offsets (flattened tuple, C-order concat)
#define OFF_SCORE 0
#define OFF_Y     1
#define OFF_YPRED 32769
#define OFF_YLOW  65537
#define OFF_YHIGH 655361
#define OFF_ERR   1245185
#define OFF_QLOW  1253377
#define OFF_QHIGH 1843201
// total 2433025

__constant__ float c_alphas[NA] = {0.05f,0.06f,0.08f,0.1f,0.12f,0.14f,0.15f,0.17f,0.19f,
                                   0.2f,0.21f,0.23f,0.25f,0.3f,0.35f,0.38f,0.4f,0.45f};

// ---------------- scratch (static device allocations) ----------------
__device__ float g_h1[NTOK2 * HID];
__device__ float g_h2[NTOK2 * HID];
__device__ float g_ln[NTOK2 * DD];
__device__ float g_qk[NTOK2 * (HH * DD)];
__device__ __nv_bfloat16 g_qb[(size_t)BB * HH * SS * DD];   // [bh][s][d]
__device__ __nv_bfloat16 g_kb[(size_t)BB * HH * SS * DD];
__device__ float g_rowsq[NROW];

// ---------------- mma.sync helpers (compute_103-safe, sm_80 era PTX) ----------
__device__ __forceinline__ uint32_t smem_u32(const void* p) {
    uint32_t a;
    asm("{ .reg .u64 t; cvta.to.shared.u64 t, %1; cvt.u32.u64 %0, t; }" : "=r"(a) : "l"(p));
    return a;
}
__device__ __forceinline__ void ldsm_x4(uint32_t& r0, uint32_t& r1, uint32_t& r2, uint32_t& r3,
                                        uint32_t addr) {
    asm volatile("ldmatrix.sync.aligned.m8n8.x4.shared.b16 {%0,%1,%2,%3}, [%4];"
                 : "=r"(r0), "=r"(r1), "=r"(r2), "=r"(r3) : "r"(addr));
}
__device__ __forceinline__ void mma_bf16(float* c, const uint32_t* a, const uint32_t* b) {
    asm volatile("mma.sync.aligned.m16n8k16.row.col.f32.bf16.bf16.f32 "
                 "{%0,%1,%2,%3}, {%4,%5,%6,%7}, {%8,%9}, {%0,%1,%2,%3};"
                 : "+f"(c[0]), "+f"(c[1]), "+f"(c[2]), "+f"(c[3])
                 : "r"(a[0]), "r"(a[1]), "r"(a[2]), "r"(a[3]), "r"(b[0]), "r"(b[1]));
}

// swizzled offset within a tile: row stride 256B, 16 chunks of 16B,
// XOR swizzle applied within each 128B half -> ldmatrix conflict-free.
__device__ __forceinline__ uint32_t tile_swz(int row, int ch) {
    return (uint32_t)row * 256u +
           (uint32_t)(((ch & 8) | ((ch ^ (row & 7)) & 7)) << 4);
}

// ---------------- generic SGEMM: C = act(A @ W + bias) (fp32, scalar FFMA) ----
__global__ __launch_bounds__(256) void sgemm_bias(
    const float* __restrict__ A, int lda,
    const float* __restrict__ W, int ldw,
    const float* __restrict__ bias,
    float* __restrict__ C, int ldc,
    int N, int K, int relu)
{
    __shared__ float As[2][8][128];
    __shared__ float Ws[2][8][128];
    const int tid = threadIdx.x;
    const int row0 = blockIdx.y * 128;
    const int col0 = blockIdx.x * 128;
    const int m0 = (tid >> 4) << 3;
    const int n0 = (tid & 15) << 3;
    const int ar = tid >> 1;
    const int ac = (tid & 1) << 2;
    const int wr = tid >> 5;
    const int wc = (tid & 31) << 2;
    const bool fullN = (col0 + 128 <= N);

    const float* Ap = A + (size_t)(row0 + ar) * lda + ac;

    float acc[8][8];
#pragma unroll
    for (int i = 0; i < 8; i++)
#pragma unroll
        for (int j = 0; j < 8; j++) acc[i][j] = 0.f;

    const int nk = K >> 3;
    float4 av = *reinterpret_cast<const float4*>(Ap);
    float4 wv;
    {
        const float* wp = W + (size_t)wr * ldw + col0 + wc;
        if (fullN) wv = *reinterpret_cast<const float4*>(wp);
        else {
            wv.x = (col0 + wc + 0 < N) ? wp[0] : 0.f;
            wv.y = (col0 + wc + 1 < N) ? wp[1] : 0.f;
            wv.z = (col0 + wc + 2 < N) ? wp[2] : 0.f;
            wv.w = (col0 + wc + 3 < N) ? wp[3] : 0.f;
        }
    }
    As[0][ac + 0][ar] = av.x; As[0][ac + 1][ar] = av.y;
    As[0][ac + 2][ar] = av.z; As[0][ac + 3][ar] = av.w;
    *reinterpret_cast<float4*>(&Ws[0][wr][wc]) = wv;
    __syncthreads();

    int buf = 0;
    for (int t = 0; t < nk; t++) {
        const bool more = (t + 1 < nk);
        if (more) {
            const int k0 = (t + 1) << 3;
            av = *reinterpret_cast<const float4*>(Ap + k0);
            const float* wp = W + (size_t)(k0 + wr) * ldw + col0 + wc;
            if (fullN) wv = *reinterpret_cast<const float4*>(wp);
            else {
                wv.x = (col0 + wc + 0 < N) ? wp[0] : 0.f;
                wv.y = (col0 + wc + 1 < N) ? wp[1] : 0.f;
                wv.z = (col0 + wc + 2 < N) ? wp[2] : 0.f;
                wv.w = (col0 + wc + 3 < N) ? wp[3] : 0.f;
            }
        }
#pragma unroll
        for (int kk = 0; kk < 8; kk++) {
            float4 a0 = *reinterpret_cast<const float4*>(&As[buf][kk][m0]);
            float4 a1 = *reinterpret_cast<const float4*>(&As[buf][kk][m0 + 4]);
            float4 w0 = *reinterpret_cast<const float4*>(&Ws[buf][kk][n0]);
            float4 w1 = *reinterpret_cast<const float4*>(&Ws[buf][kk][n0 + 4]);
            float a[8] = {a0.x, a0.y, a0.z, a0.w, a1.x, a1.y, a1.z, a1.w};
            float w[8] = {w0.x, w0.y, w0.z, w0.w, w1.x, w1.y, w1.z, w1.w};
#pragma unroll
            for (int i = 0; i < 8; i++)
#pragma unroll
                for (int j = 0; j < 8; j++) acc[i][j] = fmaf(a[i], w[j], acc[i][j]);
        }
        if (more) {
            const int nb = buf ^ 1;
            As[nb][ac + 0][ar] = av.x; As[nb][ac + 1][ar] = av.y;
            As[nb][ac + 2][ar] = av.z; As[nb][ac + 3][ar] = av.w;
            *reinterpret_cast<float4*>(&Ws[nb][wr][wc]) = wv;
            __syncthreads();
            buf = nb;
        }
    }

#pragma unroll
    for (int j = 0; j < 8; j++) {
        int c = col0 + n0 + j;
        if (c < N) {
            float bb = bias[c];
#pragma unroll
            for (int i = 0; i < 8; i++) {
                float v = acc[i][j] + bb;
                if (relu) v = fmaxf(v, 0.f);
                C[(size_t)(row0 + m0 + i) * ldc + c] = v;
            }
        }
    }
}

// ---------------- dual-source SGEMM (layer 1: true rows then sim rows) --------
__global__ __launch_bounds__(256) void sgemm_bias_dual(
    const float* __restrict__ A1, const float* __restrict__ A2, int lda,
    const float* __restrict__ W, int ldw,
    const float* __restrict__ bias,
    float* __restrict__ C, int ldc,
    int N, int K, int relu)
{
    __shared__ float As[2][8][128];
    __shared__ float Ws[2][8][128];
    const int tid = threadIdx.x;
    const int row0 = blockIdx.y * 128;
    const int col0 = blockIdx.x * 128;
    const int m0 = (tid >> 4) << 3;
    const int n0 = (tid & 15) << 3;
    const int ar = tid >> 1;
    const int ac = (tid & 1) << 2;
    const int wr = tid >> 5;
    const int wc = (tid & 31) << 2;
    const bool fullN = (col0 + 128 <= N);

    const float* Abase = (row0 < NTOK) ? A1 : A2;
    const int rbase = (row0 < NTOK) ? row0 : row0 - NTOK;
    const float* Ap = Abase + (size_t)(rbase + ar) * lda + ac;

    float acc[8][8];
#pragma unroll
    for (int i = 0; i < 8; i++)
#pragma unroll
        for (int j = 0; j < 8; j++) acc[i][j] = 0.f;

    const int nk = K >> 3;
    float4 av = *reinterpret_cast<const float4*>(Ap);
    float4 wv;
    {
        const float* wp = W + (size_t)wr * ldw + col0 + wc;
        if (fullN) wv = *reinterpret_cast<const float4*>(wp);
        else {
            wv.x = (col0 + wc + 0 < N) ? wp[0] : 0.f;
            wv.y = (col0 + wc + 1 < N) ? wp[1] : 0.f;
            wv.z = (col0 + wc + 2 < N) ? wp[2] : 0.f;
            wv.w = (col0 + wc + 3 < N) ? wp[3] : 0.f;
        }
    }
    As[0][ac + 0][ar] = av.x; As[0][ac + 1][ar] = av.y;
    As[0][ac + 2][ar] = av.z; As[0][ac + 3][ar] = av.w;
    *reinterpret_cast<float4*>(&Ws[0][wr][wc]) = wv;
    __syncthreads();

    int buf = 0;
    for (int t = 0; t < nk; t++) {
        const bool more = (t + 1 < nk);
        if (more) {
            const int k0 = (t + 1) << 3;
            av = *reinterpret_cast<const float4*>(Ap + k0);
            const float* wp = W + (size_t)(k0 + wr) * ldw + col0 + wc;
            if (fullN) wv = *reinterpret_cast<const float4*>(wp);
            else {
                wv.x = (col0 + wc + 0 < N) ? wp[0] : 0.f;
                wv.y = (col0 + wc + 1 < N) ? wp[1] : 0.f;
                wv.z = (col0 + wc + 2 < N) ? wp[2] : 0.f;
                wv.w = (col0 + wc + 3 < N) ? wp[3] : 0.f;
            }
        }
#pragma unroll
        for (int kk = 0; kk < 8; kk++) {
            float4 a0 = *reinterpret_cast<const float4*>(&As[buf][kk][m0]);
            float4 a1 = *reinterpret_cast<const float4*>(&As[buf][kk][m0 + 4]);
            float4 w0 = *reinterpret_cast<const float4*>(&Ws[buf][kk][n0]);
            float4 w1 = *reinterpret_cast<const float4*>(&Ws[buf][kk][n0 + 4]);
            float a[8] = {a0.x, a0.y, a0.z, a0.w, a1.x, a1.y, a1.z, a1.w};
            float w[8] = {w0.x, w0.y, w0.z, w0.w, w1.x, w1.y, w1.z, w1.w};
#pragma unroll
            for (int i = 0; i < 8; i++)
#pragma unroll
                for (int j = 0; j < 8; j++) acc[i][j] = fmaf(a[i], w[j], acc[i][j]);
        }
        if (more) {
            const int nb = buf ^ 1;
            As[nb][ac + 0][ar] = av.x; As[nb][ac + 1][ar] = av.y;
            As[nb][ac + 2][ar] = av.z; As[nb][ac + 3][ar] = av.w;
            *reinterpret_cast<float4*>(&Ws[nb][wr][wc]) = wv;
            __syncthreads();
            buf = nb;
        }
    }

#pragma unroll
    for (int j = 0; j < 8; j++) {
        int c = col0 + n0 + j;
        if (c < N) {
            float bb = bias[c];
#pragma unroll
            for (int i = 0; i < 8; i++) {
                float v = acc[i][j] + bb;
                if (relu) v = fmaxf(v, 0.f);
                C[(size_t)(row0 + m0 + i) * ldc + c] = v;
            }
        }
    }
}

// ---------------- L4 GEMM + LayerNorm fused -----------------------------------
// grid (128), 256 threads. Each CTA: 128 rows x full N=128, K=400.
// GEMM result staged in 64KB dynamic smem, then per-warp LN (identical math
// to the previous ln_kernel) writes g_ln directly.
__global__ __launch_bounds__(256) void sgemm_l4_ln(
    const float* __restrict__ A,
    const float* __restrict__ W,
    const float* __restrict__ bias,
    const float* __restrict__ gq, const float* __restrict__ bq,
    const float* __restrict__ gk, const float* __restrict__ bk,
    float* __restrict__ lnout)
{
    __shared__ float As[2][8][128];
    __shared__ float Ws[2][8][128];
    extern __shared__ float tile[];   // 128 x 128 floats
    const int tid = threadIdx.x;
    const int row0 = blockIdx.x * 128;
    const int m0 = (tid >> 4) << 3;
    const int n0 = (tid & 15) << 3;
    const int ar = tid >> 1;
    const int ac = (tid & 1) << 2;
    const int wr = tid >> 5;
    const int wc = (tid & 31) << 2;

    const float* Ap = A + (size_t)(row0 + ar) * HID + ac;

    float acc[8][8];
#pragma unroll
    for (int i = 0; i < 8; i++)
#pragma unroll
        for (int j = 0; j < 8; j++) acc[i][j] = 0.f;

    const int nk = HID >> 3;   // 50
    float4 av = *reinterpret_cast<const float4*>(Ap);
    float4 wv = *reinterpret_cast<const float4*>(W + (size_t)wr * DD + wc);
    As[0][ac + 0][ar] = av.x; As[0][ac + 1][ar] = av.y;
    As[0][ac + 2][ar] = av.z; As[0][ac + 3][ar] = av.w;
    *reinterpret_cast<float4*>(&Ws[0][wr][wc]) = wv;
    __syncthreads();

    int buf = 0;
    for (int t = 0; t < nk; t++) {
        const bool more = (t + 1 < nk);
        if (more) {
            const int k0 = (t + 1) << 3;
            av = *reinterpret_cast<const float4*>(Ap + k0);
            wv = *reinterpret_cast<const float4*>(W + (size_t)(k0 + wr) * DD + wc);
        }
#pragma unroll
        for (int kk = 0; kk < 8; kk++) {
            float4 a0 = *reinterpret_cast<const float4*>(&As[buf][kk][m0]);
            float4 a1 = *reinterpret_cast<const float4*>(&As[buf][kk][m0 + 4]);
            float4 w0 = *reinterpret_cast<const float4*>(&Ws[buf][kk][n0]);
            float4 w1 = *reinterpret_cast<const float4*>(&Ws[buf][kk][n0 + 4]);
            float a[8] = {a0.x, a0.y, a0.z, a0.w, a1.x, a1.y, a1.z, a1.w};
            float w[8] = {w0.x, w0.y, w0.z, w0.w, w1.x, w1.y, w1.z, w1.w};
#pragma unroll
            for (int i = 0; i < 8; i++)
#pragma unroll
                for (int j = 0; j < 8; j++) acc[i][j] = fmaf(a[i], w[j], acc[i][j]);
        }
        if (more) {
            const int nb = buf ^ 1;
            As[nb][ac + 0][ar] = av.x; As[nb][ac + 1][ar] = av.y;
            As[nb][ac + 2][ar] = av.z; As[nb][ac + 3][ar] = av.w;
            *reinterpret_cast<float4*>(&Ws[nb][wr][wc]) = wv;
            __syncthreads();
            buf = nb;
        }
    }

    // stage enc tile in smem
#pragma unroll
    for (int j = 0; j < 8; j++) {
        float bb = bias[n0 + j];
#pragma unroll
        for (int i = 0; i < 8; i++)
            tile[(m0 + i) * 128 + n0 + j] = acc[i][j] + bb;
    }
    __syncthreads();

    // LayerNorm: warp per row, 16 rows per warp (identical math to old ln_kernel)
    const int wid = tid >> 5, lane = tid & 31;
#pragma unroll 1
    for (int rr = 0; rr < 16; rr++) {
        const int r = wid * 16 + rr;
        const int grow = row0 + r;
        const float* x = &tile[r * 128];
        float v0 = x[lane], v1 = x[lane + 32], v2 = x[lane + 64], v3 = x[lane + 96];
        float s = v0 + v1 + v2 + v3;
#pragma unroll
        for (int o = 16; o; o >>= 1) s += __shfl_xor_sync(0xffffffffu, s, o);
        float mu = s * (1.f / 128.f);
        float d0 = v0 - mu, d1 = v1 - mu, d2 = v2 - mu, d3 = v3 - mu;
        float sq = d0 * d0 + d1 * d1 + d2 * d2 + d3 * d3;
#pragma unroll
        for (int o = 16; o; o >>= 1) sq += __shfl_xor_sync(0xffffffffu, sq, o);
        float rs = rsqrtf(sq * (1.f / 128.f) + 1e-5f);
        const float* g = (grow < NTOK) ? gq : gk;
        const float* be = (grow < NTOK) ? bq : bk;
        float* o = lnout + (size_t)grow * DD;
        o[lane]      = d0 * rs * g[lane]      + be[lane];
        o[lane + 32] = d1 * rs * g[lane + 32] + be[lane + 32];
        o[lane + 64] = d2 * rs * g[lane + 64] + be[lane + 64];
        o[lane + 96] = d3 * rs * g[lane + 96] + be[lane + 96];
    }
}

// ---------------- projection GEMM + bf16 conversion fused ---------------------
// grid (4,64,2): z=0 -> q (Wq, g_qb), z=1 -> k (Wk, g_kb). N=512, K=128.
__global__ __launch_bounds__(256) void sgemm_proj_cvt(
    const float* __restrict__ ln,
    const float* __restrict__ Wq, const float* __restrict__ bq,
    const float* __restrict__ Wk, const float* __restrict__ bk,
    float* __restrict__ qk)
{
    __shared__ float As[2][8][128];
    __shared__ float Ws[2][8][128];
    const int tid = threadIdx.x;
    const int z = blockIdx.z;
    const int row0 = blockIdx.y * 128;
    const int col0 = blockIdx.x * 128;
    const int m0 = (tid >> 4) << 3;
    const int n0 = (tid & 15) << 3;
    const int ar = tid >> 1;
    const int ac = (tid & 1) << 2;
    const int wr = tid >> 5;
    const int wc = (tid & 31) << 2;

    const float* A = ln + (z ? (size_t)NTOK * DD : 0);
    const float* W = z ? Wk : Wq;
    const float* bias = z ? bk : bq;
    float* C = qk + (z ? KOFF : 0);
    __nv_bfloat16* bdst = z ? g_kb : g_qb;

    const float* Ap = A + (size_t)(row0 + ar) * DD + ac;

    float acc[8][8];
#pragma unroll
    for (int i = 0; i < 8; i++)
#pragma unroll
        for (int j = 0; j < 8; j++) acc[i][j] = 0.f;

    const int nk = DD >> 3;   // 16
    float4 av = *reinterpret_cast<const float4*>(Ap);
    float4 wv = *reinterpret_cast<const float4*>(W + (size_t)wr * (HH * DD) + col0 + wc);
    As[0][ac + 0][ar] = av.x; As[0][ac + 1][ar] = av.y;
    As[0][ac + 2][ar] = av.z; As[0][ac + 3][ar] = av.w;
    *reinterpret_cast<float4*>(&Ws[0][wr][wc]) = wv;
    __syncthreads();

    int buf = 0;
    for (int t = 0; t < nk; t++) {
        const bool more = (t + 1 < nk);
        if (more) {
            const int k0 = (t + 1) << 3;
            av = *reinterpret_cast<const float4*>(Ap + k0);
            wv = *reinterpret_cast<const float4*>(W + (size_t)(k0 + wr) * (HH * DD) + col0 + wc);
        }
#pragma unroll
        for (int kk = 0; kk < 8; kk++) {
            float4 a0 = *reinterpret_cast<const float4*>(&As[buf][kk][m0]);
            float4 a1 = *reinterpret_cast<const float4*>(&As[buf][kk][m0 + 4]);
            float4 w0 = *reinterpret_cast<const float4*>(&Ws[buf][kk][n0]);
            float4 w1 = *reinterpret_cast<const float4*>(&Ws[buf][kk][n0 + 4]);
            float a[8] = {a0.x, a0.y, a0.z, a0.w, a1.x, a1.y, a1.z, a1.w};
            float w[8] = {w0.x, w0.y, w0.z, w0.w, w1.x, w1.y, w1.z, w1.w};
#pragma unroll
            for (int i = 0; i < 8; i++)
#pragma unroll
                for (int j = 0; j < 8; j++) acc[i][j] = fmaf(a[i], w[j], acc[i][j]);
        }
        if (more) {
            const int nb = buf ^ 1;
            As[nb][ac + 0][ar] = av.x; As[nb][ac + 1][ar] = av.y;
            As[nb][ac + 2][ar] = av.z; As[nb][ac + 3][ar] = av.w;
            *reinterpret_cast<float4*>(&Ws[nb][wr][wc]) = wv;
            __syncthreads();
            buf = nb;
        }
    }

    // epilogue: add bias, store fp32 (for exact rescore) + bf16 [bh][s][d]
    float vals[8][8];
#pragma unroll
    for (int j = 0; j < 8; j++) {
        int c = col0 + n0 + j;
        float bb = bias[c];
#pragma unroll
        for (int i = 0; i < 8; i++) {
            float v = acc[i][j] + bb;
            vals[i][j] = v;
            C[(size_t)(row0 + m0 + i) * (HH * DD) + c] = v;
        }
    }
    const int h = col0 >> 7;
#pragma unroll
    for (int i = 0; i < 8; i++) {
        int row = row0 + m0 + i;
        int b = row >> 11, s = row & 2047;
        __nv_bfloat16* drow = bdst + (((size_t)(b * HH + h) * SS + s)) * DD + (n0);
#pragma unroll
        for (int jp = 0; jp < 4; jp++) {
            __nv_bfloat162 p = __floats2bfloat162_rn(vals[i][2 * jp], vals[i][2 * jp + 1]);
            *reinterpret_cast<uint32_t*>(drow + 2 * jp) = *reinterpret_cast<uint32_t*>(&p);
        }
    }
}

// ---------------- fused scores MMA + top-32 + exact rescore + quantiles -------
// grid (32 row-tiles of 64, 16 bh), 256 threads (8 warps, warp tile 16x64).
// 2 CTAs/SM (smem 87.7KB). Top-32 in registers distributed across each warp.
#define SM_QT   0          // Q bf16 tile 64x128, 16384 B (swizzled, 256B row stride)
#define SM_KT   16384      // K bf16 tile 128x128, 32768 B
#define SM_SC   49152      // scores f32 [64][132] = 33792 B
#define SM_QF   82944      // per-warp q fp32 row [8][128] = 4096 B
#define SM_SRT  87040      // per-warp sorted errs [8][20] = 640 B
#define SM_FUSED_TOTAL 87680

__global__ __launch_bounds__(256, 2) void fused_scores_topk(
    const float* __restrict__ qk,
    const float* __restrict__ errors,
    const float* __restrict__ y,
    const float* __restrict__ y_pred,
    float* __restrict__ out)
{
    extern __shared__ char smem[];
    const uint32_t sb = smem_u32(smem);
    float* sc  = reinterpret_cast<float*>(smem + SM_SC);
    float* qf  = reinterpret_cast<float*>(smem + SM_QF);
    float* srt = reinterpret_cast<float*>(smem + SM_SRT);

    const int tid = threadIdx.x;
    const int wid = tid >> 5, lane = tid & 31;
    const int rt0 = blockIdx.x * 64;      // q row tile base
    const int bh = blockIdx.y;
    const int b = bh >> 2, h = bh & 3;
    const float ninf = __int_as_float(0xff800000);
    const unsigned FULL = 0xffffffffu;

    float tv[8];
    int   ti[8];
#pragma unroll
    for (int rr = 0; rr < 8; rr++) { tv[rr] = ninf; ti[rr] = 0; }

    // load Q tile 64x128 (swizzled): 1024 chunks
    const __nv_bfloat16* qsrc = g_qb + ((size_t)bh * SS + rt0) * DD;
#pragma unroll
    for (int i = 0; i < 4; i++) {
        int idx = tid + i * 256;          // 0..1023
        int row = idx >> 4, ch = idx & 15;
        *reinterpret_cast<uint4*>(smem + SM_QT + tile_swz(row, ch)) =
            *reinterpret_cast<const uint4*>(qsrc + (size_t)row * DD + ch * 8);
    }

    const int wm0 = (wid & 3) * 16;       // 4 m-warps (16 rows each)
    const int wn0 = (wid >> 2) * 64;      // 2 n-warps (64 cols each)

    uint32_t abase; int ax;
    {
        int r = wm0 + (lane & 15);
        abase = sb + SM_QT + (uint32_t)r * 256u;
        ax = r & 7;
    }
    const int alb = lane >> 4;
    uint32_t bbase[4]; int bx[4];
#pragma unroll
    for (int nf2 = 0; nf2 < 4; nf2++) {
        int r = wn0 + nf2 * 16 + (lane & 7) + ((lane & 16) >> 1);
        bbase[nf2] = sb + SM_KT + (uint32_t)r * 256u;
        bx[nf2] = r & 7;
    }
    const int blb = (lane >> 3) & 1;

    const float scale = 0.08838834764831845f;   // 1/sqrt(128)

    for (int ct = 0; ct < 16; ct++) {
        __syncthreads();
        const __nv_bfloat16* ksrc = g_kb + ((size_t)bh * SS + ct * 128) * DD;
#pragma unroll
        for (int i = 0; i < 8; i++) {
            int idx = tid + i * 256;
            int row = idx >> 4, ch = idx & 15;
            *reinterpret_cast<uint4*>(smem + SM_KT + tile_swz(row, ch)) =
                *reinterpret_cast<const uint4*>(ksrc + (size_t)row * DD + ch * 8);
        }
        __syncthreads();

        float acc[8][4];
#pragma unroll
        for (int nf = 0; nf < 8; nf++)
#pragma unroll
            for (int i = 0; i < 4; i++) acc[nf][i] = 0.f;

#pragma unroll
        for (int s = 0; s < 8; s++) {
            uint32_t a[4], bfr[8][2];
            const int ca = 2 * s + alb;
            const int cb = 2 * s + blb;
            ldsm_x4(a[0], a[1], a[2], a[3],
                    abase + (uint32_t)(((ca & 8) | ((ca ^ ax) & 7)) << 4));
#pragma unroll
            for (int nf2 = 0; nf2 < 4; nf2++) {
                uint32_t r0, r1, r2, r3;
                ldsm_x4(r0, r1, r2, r3,
                        bbase[nf2] + (uint32_t)(((cb & 8) | ((cb ^ bx[nf2]) & 7)) << 4));
                bfr[nf2 * 2][0] = r0; bfr[nf2 * 2][1] = r1;
                bfr[nf2 * 2 + 1][0] = r2; bfr[nf2 * 2 + 1][1] = r3;
            }
#pragma unroll
            for (int nf = 0; nf < 8; nf++)
                mma_bf16(acc[nf], a, bfr[nf]);
        }

        const int qr = lane >> 2, qc = (lane & 3) * 2;
        {
            int r1 = wm0 + qr;
            int r2 = r1 + 8;
            int gr1 = rt0 + r1, gr2 = rt0 + r2;
#pragma unroll
            for (int nf = 0; nf < 8; nf++) {
                int cl = wn0 + nf * 8 + qc;
                int gc = ct * 128 + cl;
                float2 v1, v2;
                v1.x = (gr1 == gc)     ? ninf : acc[nf][0] * scale;
                v1.y = (gr1 == gc + 1) ? ninf : acc[nf][1] * scale;
                v2.x = (gr2 == gc)     ? ninf : acc[nf][2] * scale;
                v2.y = (gr2 == gc + 1) ? ninf : acc[nf][3] * scale;
                *reinterpret_cast<float2*>(&sc[r1 * 132 + cl]) = v1;
                *reinterpret_cast<float2*>(&sc[r2 * 132 + cl]) = v2;
            }
        }
        __syncthreads();

#pragma unroll
        for (int rr = 0; rr < 8; rr++) {
            const int r = wid * 8 + rr;
            float thr = __shfl_sync(FULL, tv[rr], 31);
#pragma unroll
            for (int j = 0; j < 4; j++) {
                float x = sc[r * 132 + lane + 32 * j];
                unsigned m = __ballot_sync(FULL, x > thr);
                while (m) {
                    int ld = __ffs(m) - 1; m &= m - 1;
                    float bv = __shfl_sync(FULL, x, ld);
                    if (bv > thr) {
                        int bc = ct * 128 + 32 * j + ld;
                        unsigned gt = __ballot_sync(FULL, tv[rr] > bv);
                        int pos = __popc(gt);
                        float pv = __shfl_up_sync(FULL, tv[rr], 1);
                        int   pi = __shfl_up_sync(FULL, ti[rr], 1);
                        if (lane == pos)      { tv[rr] = bv; ti[rr] = bc; }
                        else if (lane > pos)  { tv[rr] = pv; ti[rr] = pi; }
                        thr = __shfl_sync(FULL, tv[rr], 31);
                    }
                }
            }
        }
    }
    __syncthreads();

#pragma unroll
    for (int rr = 0; rr < 8; rr++) {
        const int r = wid * 8 + rr;
        const int sgl = rt0 + r;
        const float* qrow = qk + ((size_t)(b * SS + sgl)) * (HH * DD) + h * DD;
        *reinterpret_cast<float4*>(&qf[wid * 128 + lane * 4]) =
            *reinterpret_cast<const float4*>(qrow + lane * 4);
        __syncwarp();

        const int my_m = ti[rr];
        const float* krow = qk + KOFF + ((size_t)(b * SS + my_m)) * (HH * DD) + h * DD;
        float ex = 0.f;
#pragma unroll
        for (int d4 = 0; d4 < 32; d4++) {
            float4 kv = *reinterpret_cast<const float4*>(krow + d4 * 4);
            float4 qv = *reinterpret_cast<const float4*>(&qf[wid * 128 + d4 * 4]);
            ex = fmaf(qv.x, kv.x, ex);
            ex = fmaf(qv.y, kv.y, ex);
            ex = fmaf(qv.z, kv.z, ex);
            ex = fmaf(qv.w, kv.w, ex);
        }

        int rank_sel = 0;
#pragma unroll
        for (int j = 0; j < NSEL; j++) {
            float sj = __shfl_sync(FULL, ex, j);
            int   mj = __shfl_sync(FULL, my_m, j);
            if ((sj > ex) || (sj == ex && mj < my_m)) rank_sel++;
        }
        const bool selected = (rank_sel < KK);

        float e = selected ? errors[((size_t)(b * SS + my_m)) * 4 + 0] : 0.f;

        int rank_e = 0;
#pragma unroll
        for (int j = 0; j < NSEL; j++) {
            float ej  = __shfl_sync(FULL, e, j);
            int   rsj = __shfl_sync(FULL, rank_sel, j);
            if (selected && rsj < KK && ((ej < e) || (ej == e && rsj < rank_sel))) rank_e++;
        }
        if (selected) srt[wid * KK + rank_e] = e;
        __syncwarp();

        const float yp = y_pred[((size_t)(b * SS + sgl)) * 4 + 0];
        float ql = 0.f, qh = 0.f;
        if (lane < NA) {
            float alpha = c_alphas[lane];
            float pl = 0.5f * alpha * (float)(KK - 1);
            int il = (int)pl; float fl = pl - (float)il;
            ql = srt[wid * KK + il] + fl * (srt[wid * KK + il + 1] - srt[wid * KK + il]);
            float ph = (1.f - 0.5f * alpha) * (float)(KK - 1);
            int ih = (int)ph; float fh = ph - (float)ih;
            qh = srt[wid * KK + ih] + fh * (srt[wid * KK + ih + 1] - srt[wid * KK + ih]);
            size_t oidx = ((size_t)((h * BB + b) * NA + lane)) * SS + sgl;
            out[OFF_QLOW  + oidx] = ql;
            out[OFF_QHIGH + oidx] = qh;
            out[OFF_YLOW  + oidx] = ql + yp;
            out[OFF_YHIGH + oidx] = qh + yp;
        }

        float t = ql + qh;
#pragma unroll
        for (int o = 16; o; o >>= 1) t += __shfl_down_sync(FULL, t, o);
        if (lane == 0) {
            float me = t * (1.f / 36.f);
            float yt = y[((size_t)(b * SS + sgl)) * 4 + 0];
            float d = yt - (me + yp);
            g_rowsq[(size_t)(b * HH + h) * SS + sgl] = d * d;
        }
        __syncwarp();
    }
}

// ---------------- passthrough copies ----------------
__global__ void copy_kernel(const float* __restrict__ y,
                            const float* __restrict__ yp,
                            const float* __restrict__ err,
                            float* __restrict__ out)
{
    int i = blockIdx.x * blockDim.x + threadIdx.x;
    if (i < 32768) out[OFF_Y + i] = y[i];
    else if (i < 65536) out[OFF_YPRED + (i - 32768)] = yp[i - 32768];
    else if (i < 73728) { int j = i - 65536; out[OFF_ERR + j] = err[(size_t)j * 4]; }
}

// ---------------- final scalar reduce ----------------
__global__ void reduce_kernel(float* __restrict__ out)
{
    __shared__ float sh[1024];
    float s = 0.f;
    for (int i = threadIdx.x; i < NROW; i += 1024) s += g_rowsq[i];
    sh[threadIdx.x] = s;
    __syncthreads();
    for (int o = 512; o; o >>= 1) {
        if (threadIdx.x < o) sh[threadIdx.x] += sh[threadIdx.x + o];
        __syncthreads();
    }
    if (threadIdx.x == 0) out[OFF_SCORE] = sh[0] * (1.f / (float)NROW);
}

// ---------------- launch ----------------
extern "C" void kernel_launch(void* const* d_in, const int* in_sizes, int n_in,
                              void* d_out, int out_size)
{
    const float* Xt   = (const float*)d_in[0];
    const float* Xs   = (const float*)d_in[1];
    const float* err  = (const float*)d_in[2];
    const float* y    = (const float*)d_in[3];
    const float* ypr  = (const float*)d_in[4];
    const float* W1   = (const float*)d_in[5];
    const float* b1   = (const float*)d_in[6];
    const float* W2   = (const float*)d_in[7];
    const float* b2   = (const float*)d_in[8];
    const float* W3   = (const float*)d_in[9];
    const float* b3   = (const float*)d_in[10];
    const float* W4   = (const float*)d_in[11];
    const float* b4   = (const float*)d_in[12];
    const float* Wq   = (const float*)d_in[13];
    const float* bq   = (const float*)d_in[14];
    const float* Wk   = (const float*)d_in[15];
    const float* bk   = (const float*)d_in[16];
    const float* gq   = (const float*)d_in[17];
    const float* betaq= (const float*)d_in[18];
    const float* gk   = (const float*)d_in[19];
    const float* betak= (const float*)d_in[20];
    float* out = (float*)d_out;

    float *p_h1, *p_h2, *p_ln, *p_qk;
    cudaGetSymbolAddress((void**)&p_h1, g_h1);
    cudaGetSymbolAddress((void**)&p_h2, g_h2);
    cudaGetSymbolAddress((void**)&p_ln, g_ln);
    cudaGetSymbolAddress((void**)&p_qk, g_qk);

    cudaFuncSetAttribute(sgemm_l4_ln,
                         cudaFuncAttributeMaxDynamicSharedMemorySize, 65536);
    cudaFuncSetAttribute(fused_scores_topk,
                         cudaFuncAttributeMaxDynamicSharedMemorySize, SM_FUSED_TOTAL);

    // 0: MLP layer 1 (dual source: true rows [0,8192), sim rows [8192,16384))
    sgemm_bias_dual<<<dim3(4, 128), 256>>>(Xt, Xs, INF_DIM, W1, HID, b1, p_h1, HID, HID, INF_DIM, 1);
    // 1,2: layers 2,3
    sgemm_bias<<<dim3(4, 128), 256>>>(p_h1, HID, W2, HID, b2, p_h2, HID, HID, HID, 1);
    sgemm_bias<<<dim3(4, 128), 256>>>(p_h2, HID, W3, HID, b3, p_h1, HID, HID, HID, 1);
    // 3: layer 4 + LayerNorm fused -> g_ln
    sgemm_l4_ln<<<128, 256, 65536>>>(p_h1, W4, b4, gq, betaq, gk, betak, p_ln);
    // 4: projections q/k + bf16 conversion fused
    sgemm_proj_cvt<<<dim3(4, 64, 2), 256>>>(p_ln, Wq, bq, Wk, bk, p_qk);
    // 5: fused scores MMA + register top-32 + exact fp32 rescore + quantiles
    fused_scores_topk<<<dim3(32, 16), 256, SM_FUSED_TOTAL>>>(p_qk, err, y, ypr, out);
    // 6: passthrough copies
    copy_kernel<<<288, 256>>>(y, ypr, err, out);
    // 7: scalar score
    reduce_kernel<<<1, 1024>>>(out);
}

// round 17
// speedup vs baseline: 1.0709x; 1.0709x over previous
#include <cuda_runtime.h>
#include <cuda_bf16.h>
#include <math.h>
#include <stdint.h>

// ---------------- problem constants ----------------
#define BB 4
#define SS 2048
#define INF_DIM 64
#define DD 128
#define HID 400
#define HH 4
#define KK 20
#define NSEL 32
#define NA 18

#define NTOK 8192          // B*S
#define NTOK2 16384        // 2*B*S (true + sim)
#define NROW 32768         // B*H*S
#define KOFF ((size_t)NTOK * (HH * DD))   // offset of k rows inside g_qk

// output offsets (flattened tuple, C-order concat)
#define OFF_SCORE 0
#define OFF_Y     1
#define OFF_YPRED 32769
#define OFF_YLOW  65537
#define OFF_YHIGH 655361
#define OFF_ERR   1245185
#define OFF_QLOW  1253377
#define OFF_QHIGH 1843201
// total 2433025

__constant__ float c_alphas[NA] = {0.05f,0.06f,0.08f,0.1f,0.12f,0.14f,0.15f,0.17f,0.19f,
                                   0.2f,0.21f,0.23f,0.25f,0.3f,0.35f,0.38f,0.4f,0.45f};

// ---------------- scratch (static device allocations) ----------------
__device__ float g_h1[NTOK2 * HID];
__device__ float g_h2[NTOK2 * HID];
__device__ float g_ln[NTOK2 * DD];
__device__ float g_qk[NTOK2 * (HH * DD)];
__device__ __nv_bfloat16 g_qb[(size_t)BB * HH * SS * DD];   // [bh][s][d]
__device__ __nv_bfloat16 g_kb[(size_t)BB * HH * SS * DD];
__device__ float g_rowsq[NROW];

// ---------------- mma.sync helpers (compute_103-safe, sm_80 era PTX) ----------
__device__ __forceinline__ uint32_t smem_u32(const void* p) {
    uint32_t a;
    asm("{ .reg .u64 t; cvta.to.shared.u64 t, %1; cvt.u32.u64 %0, t; }" : "=r"(a) : "l"(p));
    return a;
}
__device__ __forceinline__ void ldsm_x4(uint32_t& r0, uint32_t& r1, uint32_t& r2, uint32_t& r3,
                                        uint32_t addr) {
    asm volatile("ldmatrix.sync.aligned.m8n8.x4.shared.b16 {%0,%1,%2,%3}, [%4];"
                 : "=r"(r0), "=r"(r1), "=r"(r2), "=r"(r3) : "r"(addr));
}
__device__ __forceinline__ void mma_bf16(float* c, const uint32_t* a, const uint32_t* b) {
    asm volatile("mma.sync.aligned.m16n8k16.row.col.f32.bf16.bf16.f32 "
                 "{%0,%1,%2,%3}, {%4,%5,%6,%7}, {%8,%9}, {%0,%1,%2,%3};"
                 : "+f"(c[0]), "+f"(c[1]), "+f"(c[2]), "+f"(c[3])
                 : "r"(a[0]), "r"(a[1]), "r"(a[2]), "r"(a[3]), "r"(b[0]), "r"(b[1]));
}

// swizzled offset within a tile: row stride 256B, 16 chunks of 16B,
// XOR swizzle applied within each 128B half -> ldmatrix conflict-free.
__device__ __forceinline__ uint32_t tile_swz(int row, int ch) {
    return (uint32_t)row * 256u +
           (uint32_t)(((ch & 8) | ((ch ^ (row & 7)) & 7)) << 4);
}

// ---------------- generic SGEMM: C = act(A @ W + bias) (fp32, scalar FFMA) ----
__global__ __launch_bounds__(256) void sgemm_bias(
    const float* __restrict__ A, int lda,
    const float* __restrict__ W, int ldw,
    const float* __restrict__ bias,
    float* __restrict__ C, int ldc,
    int N, int K, int relu)
{
    __shared__ float As[2][8][128];
    __shared__ float Ws[2][8][128];
    const int tid = threadIdx.x;
    const int row0 = blockIdx.y * 128;
    const int col0 = blockIdx.x * 128;
    const int m0 = (tid >> 4) << 3;
    const int n0 = (tid & 15) << 3;
    const int ar = tid >> 1;
    const int ac = (tid & 1) << 2;
    const int wr = tid >> 5;
    const int wc = (tid & 31) << 2;
    const bool fullN = (col0 + 128 <= N);

    const float* Ap = A + (size_t)(row0 + ar) * lda + ac;

    float acc[8][8];
#pragma unroll
    for (int i = 0; i < 8; i++)
#pragma unroll
        for (int j = 0; j < 8; j++) acc[i][j] = 0.f;

    const int nk = K >> 3;
    float4 av = *reinterpret_cast<const float4*>(Ap);
    float4 wv;
    {
        const float* wp = W + (size_t)wr * ldw + col0 + wc;
        if (fullN) wv = *reinterpret_cast<const float4*>(wp);
        else {
            wv.x = (col0 + wc + 0 < N) ? wp[0] : 0.f;
            wv.y = (col0 + wc + 1 < N) ? wp[1] : 0.f;
            wv.z = (col0 + wc + 2 < N) ? wp[2] : 0.f;
            wv.w = (col0 + wc + 3 < N) ? wp[3] : 0.f;
        }
    }
    As[0][ac + 0][ar] = av.x; As[0][ac + 1][ar] = av.y;
    As[0][ac + 2][ar] = av.z; As[0][ac + 3][ar] = av.w;
    *reinterpret_cast<float4*>(&Ws[0][wr][wc]) = wv;
    __syncthreads();

    int buf = 0;
    for (int t = 0; t < nk; t++) {
        const bool more = (t + 1 < nk);
        if (more) {
            const int k0 = (t + 1) << 3;
            av = *reinterpret_cast<const float4*>(Ap + k0);
            const float* wp = W + (size_t)(k0 + wr) * ldw + col0 + wc;
            if (fullN) wv = *reinterpret_cast<const float4*>(wp);
            else {
                wv.x = (col0 + wc + 0 < N) ? wp[0] : 0.f;
                wv.y = (col0 + wc + 1 < N) ? wp[1] : 0.f;
                wv.z = (col0 + wc + 2 < N) ? wp[2] : 0.f;
                wv.w = (col0 + wc + 3 < N) ? wp[3] : 0.f;
            }
        }
#pragma unroll
        for (int kk = 0; kk < 8; kk++) {
            float4 a0 = *reinterpret_cast<const float4*>(&As[buf][kk][m0]);
            float4 a1 = *reinterpret_cast<const float4*>(&As[buf][kk][m0 + 4]);
            float4 w0 = *reinterpret_cast<const float4*>(&Ws[buf][kk][n0]);
            float4 w1 = *reinterpret_cast<const float4*>(&Ws[buf][kk][n0 + 4]);
            float a[8] = {a0.x, a0.y, a0.z, a0.w, a1.x, a1.y, a1.z, a1.w};
            float w[8] = {w0.x, w0.y, w0.z, w0.w, w1.x, w1.y, w1.z, w1.w};
#pragma unroll
            for (int i = 0; i < 8; i++)
#pragma unroll
                for (int j = 0; j < 8; j++) acc[i][j] = fmaf(a[i], w[j], acc[i][j]);
        }
        if (more) {
            const int nb = buf ^ 1;
            As[nb][ac + 0][ar] = av.x; As[nb][ac + 1][ar] = av.y;
            As[nb][ac + 2][ar] = av.z; As[nb][ac + 3][ar] = av.w;
            *reinterpret_cast<float4*>(&Ws[nb][wr][wc]) = wv;
            __syncthreads();
            buf = nb;
        }
    }

#pragma unroll
    for (int j = 0; j < 8; j++) {
        int c = col0 + n0 + j;
        if (c < N) {
            float bb = bias[c];
#pragma unroll
            for (int i = 0; i < 8; i++) {
                float v = acc[i][j] + bb;
                if (relu) v = fmaxf(v, 0.f);
                C[(size_t)(row0 + m0 + i) * ldc + c] = v;
            }
        }
    }
}

// ---------------- dual-source SGEMM (layer 1: true rows then sim rows) --------
__global__ __launch_bounds__(256) void sgemm_bias_dual(
    const float* __restrict__ A1, const float* __restrict__ A2, int lda,
    const float* __restrict__ W, int ldw,
    const float* __restrict__ bias,
    float* __restrict__ C, int ldc,
    int N, int K, int relu)
{
    __shared__ float As[2][8][128];
    __shared__ float Ws[2][8][128];
    const int tid = threadIdx.x;
    const int row0 = blockIdx.y * 128;
    const int col0 = blockIdx.x * 128;
    const int m0 = (tid >> 4) << 3;
    const int n0 = (tid & 15) << 3;
    const int ar = tid >> 1;
    const int ac = (tid & 1) << 2;
    const int wr = tid >> 5;
    const int wc = (tid & 31) << 2;
    const bool fullN = (col0 + 128 <= N);

    const float* Abase = (row0 < NTOK) ? A1 : A2;
    const int rbase = (row0 < NTOK) ? row0 : row0 - NTOK;
    const float* Ap = Abase + (size_t)(rbase + ar) * lda + ac;

    float acc[8][8];
#pragma unroll
    for (int i = 0; i < 8; i++)
#pragma unroll
        for (int j = 0; j < 8; j++) acc[i][j] = 0.f;

    const int nk = K >> 3;
    float4 av = *reinterpret_cast<const float4*>(Ap);
    float4 wv;
    {
        const float* wp = W + (size_t)wr * ldw + col0 + wc;
        if (fullN) wv = *reinterpret_cast<const float4*>(wp);
        else {
            wv.x = (col0 + wc + 0 < N) ? wp[0] : 0.f;
            wv.y = (col0 + wc + 1 < N) ? wp[1] : 0.f;
            wv.z = (col0 + wc + 2 < N) ? wp[2] : 0.f;
            wv.w = (col0 + wc + 3 < N) ? wp[3] : 0.f;
        }
    }
    As[0][ac + 0][ar] = av.x; As[0][ac + 1][ar] = av.y;
    As[0][ac + 2][ar] = av.z; As[0][ac + 3][ar] = av.w;
    *reinterpret_cast<float4*>(&Ws[0][wr][wc]) = wv;
    __syncthreads();

    int buf = 0;
    for (int t = 0; t < nk; t++) {
        const bool more = (t + 1 < nk);
        if (more) {
            const int k0 = (t + 1) << 3;
            av = *reinterpret_cast<const float4*>(Ap + k0);
            const float* wp = W + (size_t)(k0 + wr) * ldw + col0 + wc;
            if (fullN) wv = *reinterpret_cast<const float4*>(wp);
            else {
                wv.x = (col0 + wc + 0 < N) ? wp[0] : 0.f;
                wv.y = (col0 + wc + 1 < N) ? wp[1] : 0.f;
                wv.z = (col0 + wc + 2 < N) ? wp[2] : 0.f;
                wv.w = (col0 + wc + 3 < N) ? wp[3] : 0.f;
            }
        }
#pragma unroll
        for (int kk = 0; kk < 8; kk++) {
            float4 a0 = *reinterpret_cast<const float4*>(&As[buf][kk][m0]);
            float4 a1 = *reinterpret_cast<const float4*>(&As[buf][kk][m0 + 4]);
            float4 w0 = *reinterpret_cast<const float4*>(&Ws[buf][kk][n0]);
            float4 w1 = *reinterpret_cast<const float4*>(&Ws[buf][kk][n0 + 4]);
            float a[8] = {a0.x, a0.y, a0.z, a0.w, a1.x, a1.y, a1.z, a1.w};
            float w[8] = {w0.x, w0.y, w0.z, w0.w, w1.x, w1.y, w1.z, w1.w};
#pragma unroll
            for (int i = 0; i < 8; i++)
#pragma unroll
                for (int j = 0; j < 8; j++) acc[i][j] = fmaf(a[i], w[j], acc[i][j]);
        }
        if (more) {
            const int nb = buf ^ 1;
            As[nb][ac + 0][ar] = av.x; As[nb][ac + 1][ar] = av.y;
            As[nb][ac + 2][ar] = av.z; As[nb][ac + 3][ar] = av.w;
            *reinterpret_cast<float4*>(&Ws[nb][wr][wc]) = wv;
            __syncthreads();
            buf = nb;
        }
    }

#pragma unroll
    for (int j = 0; j < 8; j++) {
        int c = col0 + n0 + j;
        if (c < N) {
            float bb = bias[c];
#pragma unroll
            for (int i = 0; i < 8; i++) {
                float v = acc[i][j] + bb;
                if (relu) v = fmaxf(v, 0.f);
                C[(size_t)(row0 + m0 + i) * ldc + c] = v;
            }
        }
    }
}

// ---------------- L4 GEMM + LayerNorm fused -----------------------------------
// grid (128), 256 threads. Each CTA: 128 rows x full N=128, K=400.
__global__ __launch_bounds__(256) void sgemm_l4_ln(
    const float* __restrict__ A,
    const float* __restrict__ W,
    const float* __restrict__ bias,
    const float* __restrict__ gq, const float* __restrict__ bq,
    const float* __restrict__ gk, const float* __restrict__ bk,
    float* __restrict__ lnout)
{
    __shared__ float As[2][8][128];
    __shared__ float Ws[2][8][128];
    extern __shared__ float tile[];   // 128 x 128 floats
    const int tid = threadIdx.x;
    const int row0 = blockIdx.x * 128;
    const int m0 = (tid >> 4) << 3;
    const int n0 = (tid & 15) << 3;
    const int ar = tid >> 1;
    const int ac = (tid & 1) << 2;
    const int wr = tid >> 5;
    const int wc = (tid & 31) << 2;

    const float* Ap = A + (size_t)(row0 + ar) * HID + ac;

    float acc[8][8];
#pragma unroll
    for (int i = 0; i < 8; i++)
#pragma unroll
        for (int j = 0; j < 8; j++) acc[i][j] = 0.f;

    const int nk = HID >> 3;   // 50
    float4 av = *reinterpret_cast<const float4*>(Ap);
    float4 wv = *reinterpret_cast<const float4*>(W + (size_t)wr * DD + wc);
    As[0][ac + 0][ar] = av.x; As[0][ac + 1][ar] = av.y;
    As[0][ac + 2][ar] = av.z; As[0][ac + 3][ar] = av.w;
    *reinterpret_cast<float4*>(&Ws[0][wr][wc]) = wv;
    __syncthreads();

    int buf = 0;
    for (int t = 0; t < nk; t++) {
        const bool more = (t + 1 < nk);
        if (more) {
            const int k0 = (t + 1) << 3;
            av = *reinterpret_cast<const float4*>(Ap + k0);
            wv = *reinterpret_cast<const float4*>(W + (size_t)(k0 + wr) * DD + wc);
        }
#pragma unroll
        for (int kk = 0; kk < 8; kk++) {
            float4 a0 = *reinterpret_cast<const float4*>(&As[buf][kk][m0]);
            float4 a1 = *reinterpret_cast<const float4*>(&As[buf][kk][m0 + 4]);
            float4 w0 = *reinterpret_cast<const float4*>(&Ws[buf][kk][n0]);
            float4 w1 = *reinterpret_cast<const float4*>(&Ws[buf][kk][n0 + 4]);
            float a[8] = {a0.x, a0.y, a0.z, a0.w, a1.x, a1.y, a1.z, a1.w};
            float w[8] = {w0.x, w0.y, w0.z, w0.w, w1.x, w1.y, w1.z, w1.w};
#pragma unroll
            for (int i = 0; i < 8; i++)
#pragma unroll
                for (int j = 0; j < 8; j++) acc[i][j] = fmaf(a[i], w[j], acc[i][j]);
        }
        if (more) {
            const int nb = buf ^ 1;
            As[nb][ac + 0][ar] = av.x; As[nb][ac + 1][ar] = av.y;
            As[nb][ac + 2][ar] = av.z; As[nb][ac + 3][ar] = av.w;
            *reinterpret_cast<float4*>(&Ws[nb][wr][wc]) = wv;
            __syncthreads();
            buf = nb;
        }
    }

    // stage enc tile in smem
#pragma unroll
    for (int j = 0; j < 8; j++) {
        float bb = bias[n0 + j];
#pragma unroll
        for (int i = 0; i < 8; i++)
            tile[(m0 + i) * 128 + n0 + j] = acc[i][j] + bb;
    }
    __syncthreads();

    // LayerNorm: warp per row, 16 rows per warp (identical math to old ln_kernel)
    const int wid = tid >> 5, lane = tid & 31;
#pragma unroll 1
    for (int rr = 0; rr < 16; rr++) {
        const int r = wid * 16 + rr;
        const int grow = row0 + r;
        const float* x = &tile[r * 128];
        float v0 = x[lane], v1 = x[lane + 32], v2 = x[lane + 64], v3 = x[lane + 96];
        float s = v0 + v1 + v2 + v3;
#pragma unroll
        for (int o = 16; o; o >>= 1) s += __shfl_xor_sync(0xffffffffu, s, o);
        float mu = s * (1.f / 128.f);
        float d0 = v0 - mu, d1 = v1 - mu, d2 = v2 - mu, d3 = v3 - mu;
        float sq = d0 * d0 + d1 * d1 + d2 * d2 + d3 * d3;
#pragma unroll
        for (int o = 16; o; o >>= 1) sq += __shfl_xor_sync(0xffffffffu, sq, o);
        float rs = rsqrtf(sq * (1.f / 128.f) + 1e-5f);
        const float* g = (grow < NTOK) ? gq : gk;
        const float* be = (grow < NTOK) ? bq : bk;
        float* o = lnout + (size_t)grow * DD;
        o[lane]      = d0 * rs * g[lane]      + be[lane];
        o[lane + 32] = d1 * rs * g[lane + 32] + be[lane + 32];
        o[lane + 64] = d2 * rs * g[lane + 64] + be[lane + 64];
        o[lane + 96] = d3 * rs * g[lane + 96] + be[lane + 96];
    }
}

// ---------------- projection GEMM + bf16 conversion fused ---------------------
// grid (4,64,2): z=0 -> q (Wq, g_qb), z=1 -> k (Wk, g_kb). N=512, K=128.
__global__ __launch_bounds__(256) void sgemm_proj_cvt(
    const float* __restrict__ ln,
    const float* __restrict__ Wq, const float* __restrict__ bq,
    const float* __restrict__ Wk, const float* __restrict__ bk,
    float* __restrict__ qk)
{
    __shared__ float As[2][8][128];
    __shared__ float Ws[2][8][128];
    const int tid = threadIdx.x;
    const int z = blockIdx.z;
    const int row0 = blockIdx.y * 128;
    const int col0 = blockIdx.x * 128;
    const int m0 = (tid >> 4) << 3;
    const int n0 = (tid & 15) << 3;
    const int ar = tid >> 1;
    const int ac = (tid & 1) << 2;
    const int wr = tid >> 5;
    const int wc = (tid & 31) << 2;

    const float* A = ln + (z ? (size_t)NTOK * DD : 0);
    const float* W = z ? Wk : Wq;
    const float* bias = z ? bk : bq;
    float* C = qk + (z ? KOFF : 0);
    __nv_bfloat16* bdst = z ? g_kb : g_qb;

    const float* Ap = A + (size_t)(row0 + ar) * DD + ac;

    float acc[8][8];
#pragma unroll
    for (int i = 0; i < 8; i++)
#pragma unroll
        for (int j = 0; j < 8; j++) acc[i][j] = 0.f;

    const int nk = DD >> 3;   // 16
    float4 av = *reinterpret_cast<const float4*>(Ap);
    float4 wv = *reinterpret_cast<const float4*>(W + (size_t)wr * (HH * DD) + col0 + wc);
    As[0][ac + 0][ar] = av.x; As[0][ac + 1][ar] = av.y;
    As[0][ac + 2][ar] = av.z; As[0][ac + 3][ar] = av.w;
    *reinterpret_cast<float4*>(&Ws[0][wr][wc]) = wv;
    __syncthreads();

    int buf = 0;
    for (int t = 0; t < nk; t++) {
        const bool more = (t + 1 < nk);
        if (more) {
            const int k0 = (t + 1) << 3;
            av = *reinterpret_cast<const float4*>(Ap + k0);
            wv = *reinterpret_cast<const float4*>(W + (size_t)(k0 + wr) * (HH * DD) + col0 + wc);
        }
#pragma unroll
        for (int kk = 0; kk < 8; kk++) {
            float4 a0 = *reinterpret_cast<const float4*>(&As[buf][kk][m0]);
            float4 a1 = *reinterpret_cast<const float4*>(&As[buf][kk][m0 + 4]);
            float4 w0 = *reinterpret_cast<const float4*>(&Ws[buf][kk][n0]);
            float4 w1 = *reinterpret_cast<const float4*>(&Ws[buf][kk][n0 + 4]);
            float a[8] = {a0.x, a0.y, a0.z, a0.w, a1.x, a1.y, a1.z, a1.w};
            float w[8] = {w0.x, w0.y, w0.z, w0.w, w1.x, w1.y, w1.z, w1.w};
#pragma unroll
            for (int i = 0; i < 8; i++)
#pragma unroll
                for (int j = 0; j < 8; j++) acc[i][j] = fmaf(a[i], w[j], acc[i][j]);
        }
        if (more) {
            const int nb = buf ^ 1;
            As[nb][ac + 0][ar] = av.x; As[nb][ac + 1][ar] = av.y;
            As[nb][ac + 2][ar] = av.z; As[nb][ac + 3][ar] = av.w;
            *reinterpret_cast<float4*>(&Ws[nb][wr][wc]) = wv;
            __syncthreads();
            buf = nb;
        }
    }

    // epilogue: add bias, store fp32 (for exact rescore) + bf16 [bh][s][d]
    float vals[8][8];
#pragma unroll
    for (int j = 0; j < 8; j++) {
        int c = col0 + n0 + j;
        float bb = bias[c];
#pragma unroll
        for (int i = 0; i < 8; i++) {
            float v = acc[i][j] + bb;
            vals[i][j] = v;
            C[(size_t)(row0 + m0 + i) * (HH * DD) + c] = v;
        }
    }
    const int h = col0 >> 7;
#pragma unroll
    for (int i = 0; i < 8; i++) {
        int row = row0 + m0 + i;
        int b = row >> 11, s = row & 2047;
        __nv_bfloat16* drow = bdst + (((size_t)(b * HH + h) * SS + s)) * DD + (n0);
#pragma unroll
        for (int jp = 0; jp < 4; jp++) {
            __nv_bfloat162 p = __floats2bfloat162_rn(vals[i][2 * jp], vals[i][2 * jp + 1]);
            *reinterpret_cast<uint32_t*>(drow + 2 * jp) = *reinterpret_cast<uint32_t*>(&p);
        }
    }
}

// ---------------- fused scores MMA + top-32 + exact rescore + quantiles -------
// grid (32 row-tiles of 64, 16 bh), 256 threads (8 warps, warp tile 16x64).
// Top-32 in registers distributed across each warp (lane l = rank l).
// Stale-threshold insertion: thr refreshed once per j-group; over-admitted
// candidates drop naturally at pos==32 -> candidate set bit-identical.
#define SM_QT   0          // Q bf16 tile 64x128, 16384 B (swizzled, 256B row stride)
#define SM_KT   16384      // K bf16 tile 128x128, 32768 B
#define SM_SC   49152      // scores f32 [64][132] = 33792 B
#define SM_QF   82944      // per-warp q fp32 row [8][128] = 4096 B
#define SM_SRT  87040      // per-warp sorted errs [8][20] = 640 B
#define SM_FUSED_TOTAL 87680

__global__ __launch_bounds__(256, 2) void fused_scores_topk(
    const float* __restrict__ qk,
    const float* __restrict__ errors,
    const float* __restrict__ y,
    const float* __restrict__ y_pred,
    float* __restrict__ out)
{
    extern __shared__ char smem[];
    const uint32_t sb = smem_u32(smem);
    float* sc  = reinterpret_cast<float*>(smem + SM_SC);
    float* qf  = reinterpret_cast<float*>(smem + SM_QF);
    float* srt = reinterpret_cast<float*>(smem + SM_SRT);

    const int tid = threadIdx.x;
    const int wid = tid >> 5, lane = tid & 31;
    const int rt0 = blockIdx.x * 64;      // q row tile base
    const int bh = blockIdx.y;
    const int b = bh >> 2, h = bh & 3;
    const float ninf = __int_as_float(0xff800000);
    const unsigned FULL = 0xffffffffu;

    float tv[8];
    int   ti[8];
#pragma unroll
    for (int rr = 0; rr < 8; rr++) { tv[rr] = ninf; ti[rr] = 0; }

    // load Q tile 64x128 (swizzled): 1024 chunks
    const __nv_bfloat16* qsrc = g_qb + ((size_t)bh * SS + rt0) * DD;
#pragma unroll
    for (int i = 0; i < 4; i++) {
        int idx = tid + i * 256;          // 0..1023
        int row = idx >> 4, ch = idx & 15;
        *reinterpret_cast<uint4*>(smem + SM_QT + tile_swz(row, ch)) =
            *reinterpret_cast<const uint4*>(qsrc + (size_t)row * DD + ch * 8);
    }

    const int wm0 = (wid & 3) * 16;       // 4 m-warps (16 rows each)
    const int wn0 = (wid >> 2) * 64;      // 2 n-warps (64 cols each)

    uint32_t abase; int ax;
    {
        int r = wm0 + (lane & 15);
        abase = sb + SM_QT + (uint32_t)r * 256u;
        ax = r & 7;
    }
    const int alb = lane >> 4;
    uint32_t bbase[4]; int bx[4];
#pragma unroll
    for (int nf2 = 0; nf2 < 4; nf2++) {
        int r = wn0 + nf2 * 16 + (lane & 7) + ((lane & 16) >> 1);
        bbase[nf2] = sb + SM_KT + (uint32_t)r * 256u;
        bx[nf2] = r & 7;
    }
    const int blb = (lane >> 3) & 1;

    const float scale = 0.08838834764831845f;   // 1/sqrt(128)

    for (int ct = 0; ct < 16; ct++) {
        __syncthreads();
        const __nv_bfloat16* ksrc = g_kb + ((size_t)bh * SS + ct * 128) * DD;
#pragma unroll
        for (int i = 0; i < 8; i++) {
            int idx = tid + i * 256;
            int row = idx >> 4, ch = idx & 15;
            *reinterpret_cast<uint4*>(smem + SM_KT + tile_swz(row, ch)) =
                *reinterpret_cast<const uint4*>(ksrc + (size_t)row * DD + ch * 8);
        }
        __syncthreads();

        float acc[8][4];
#pragma unroll
        for (int nf = 0; nf < 8; nf++)
#pragma unroll
            for (int i = 0; i < 4; i++) acc[nf][i] = 0.f;

#pragma unroll
        for (int s = 0; s < 8; s++) {
            uint32_t a[4], bfr[8][2];
            const int ca = 2 * s + alb;
            const int cb = 2 * s + blb;
            ldsm_x4(a[0], a[1], a[2], a[3],
                    abase + (uint32_t)(((ca & 8) | ((ca ^ ax) & 7)) << 4));
#pragma unroll
            for (int nf2 = 0; nf2 < 4; nf2++) {
                uint32_t r0, r1, r2, r3;
                ldsm_x4(r0, r1, r2, r3,
                        bbase[nf2] + (uint32_t)(((cb & 8) | ((cb ^ bx[nf2]) & 7)) << 4));
                bfr[nf2 * 2][0] = r0; bfr[nf2 * 2][1] = r1;
                bfr[nf2 * 2 + 1][0] = r2; bfr[nf2 * 2 + 1][1] = r3;
            }
#pragma unroll
            for (int nf = 0; nf < 8; nf++)
                mma_bf16(acc[nf], a, bfr[nf]);
        }

        const int qr = lane >> 2, qc = (lane & 3) * 2;
        {
            int r1 = wm0 + qr;
            int r2 = r1 + 8;
            int gr1 = rt0 + r1, gr2 = rt0 + r2;
#pragma unroll
            for (int nf = 0; nf < 8; nf++) {
                int cl = wn0 + nf * 8 + qc;
                int gc = ct * 128 + cl;
                float2 v1, v2;
                v1.x = (gr1 == gc)     ? ninf : acc[nf][0] * scale;
                v1.y = (gr1 == gc + 1) ? ninf : acc[nf][1] * scale;
                v2.x = (gr2 == gc)     ? ninf : acc[nf][2] * scale;
                v2.y = (gr2 == gc + 1) ? ninf : acc[nf][3] * scale;
                *reinterpret_cast<float2*>(&sc[r1 * 132 + cl]) = v1;
                *reinterpret_cast<float2*>(&sc[r2 * 132 + cl]) = v2;
            }
        }
        __syncthreads();

        // top-32 streaming update with stale threshold (short dependent chain).
#pragma unroll
        for (int rr = 0; rr < 8; rr++) {
            const int r = wid * 8 + rr;
#pragma unroll
            for (int j = 0; j < 4; j++) {
                float thr = __shfl_sync(FULL, tv[rr], 31);   // stale for this group
                float x = sc[r * 132 + lane + 32 * j];
                unsigned m = __ballot_sync(FULL, x > thr);
                while (m) {
                    int ld = __ffs(m) - 1; m &= m - 1;
                    float bv = __shfl_sync(FULL, x, ld);
                    int bc = ct * 128 + 32 * j + ld;
                    unsigned gt = __ballot_sync(FULL, tv[rr] > bv);
                    int pos = __popc(gt);                    // 32 -> dropped
                    float pv = __shfl_up_sync(FULL, tv[rr], 1);
                    int   pi = __shfl_up_sync(FULL, ti[rr], 1);
                    if (lane == pos)      { tv[rr] = bv; ti[rr] = bc; }
                    else if (lane > pos)  { tv[rr] = pv; ti[rr] = pi; }
                }
            }
        }
    }
    __syncthreads();

#pragma unroll
    for (int rr = 0; rr < 8; rr++) {
        const int r = wid * 8 + rr;
        const int sgl = rt0 + r;
        const float* qrow = qk + ((size_t)(b * SS + sgl)) * (HH * DD) + h * DD;
        *reinterpret_cast<float4*>(&qf[wid * 128 + lane * 4]) =
            *reinterpret_cast<const float4*>(qrow + lane * 4);
        __syncwarp();

        const int my_m = ti[rr];
        const float* krow = qk + KOFF + ((size_t)(b * SS + my_m)) * (HH * DD) + h * DD;
        float ex = 0.f;
#pragma unroll
        for (int d4 = 0; d4 < 32; d4++) {
            float4 kv = *reinterpret_cast<const float4*>(krow + d4 * 4);
            float4 qv = *reinterpret_cast<const float4*>(&qf[wid * 128 + d4 * 4]);
            ex = fmaf(qv.x, kv.x, ex);
            ex = fmaf(qv.y, kv.y, ex);
            ex = fmaf(qv.z, kv.z, ex);
            ex = fmaf(qv.w, kv.w, ex);
        }

        int rank_sel = 0;
#pragma unroll
        for (int j = 0; j < NSEL; j++) {
            float sj = __shfl_sync(FULL, ex, j);
            int   mj = __shfl_sync(FULL, my_m, j);
            if ((sj > ex) || (sj == ex && mj < my_m)) rank_sel++;
        }
        const bool selected = (rank_sel < KK);

        float e = selected ? errors[((size_t)(b * SS + my_m)) * 4 + 0] : 0.f;

        int rank_e = 0;
#pragma unroll
        for (int j = 0; j < NSEL; j++) {
            float ej  = __shfl_sync(FULL, e, j);
            int   rsj = __shfl_sync(FULL, rank_sel, j);
            if (selected && rsj < KK && ((ej < e) || (ej == e && rsj < rank_sel))) rank_e++;
        }
        if (selected) srt[wid * KK + rank_e] = e;
        __syncwarp();

        const float yp = y_pred[((size_t)(b * SS + sgl)) * 4 + 0];
        float ql = 0.f, qh = 0.f;
        if (lane < NA) {
            float alpha = c_alphas[lane];
            float pl = 0.5f * alpha * (float)(KK - 1);
            int il = (int)pl; float fl = pl - (float)il;
            ql = srt[wid * KK + il] + fl * (srt[wid * KK + il + 1] - srt[wid * KK + il]);
            float ph = (1.f - 0.5f * alpha) * (float)(KK - 1);
            int ih = (int)ph; float fh = ph - (float)ih;
            qh = srt[wid * KK + ih] + fh * (srt[wid * KK + ih + 1] - srt[wid * KK + ih]);
            size_t oidx = ((size_t)((h * BB + b) * NA + lane)) * SS + sgl;
            out[OFF_QLOW  + oidx] = ql;
            out[OFF_QHIGH + oidx] = qh;
            out[OFF_YLOW  + oidx] = ql + yp;
            out[OFF_YHIGH + oidx] = qh + yp;
        }

        float t = ql + qh;
#pragma unroll
        for (int o = 16; o; o >>= 1) t += __shfl_down_sync(FULL, t, o);
        if (lane == 0) {
            float me = t * (1.f / 36.f);
            float yt = y[((size_t)(b * SS + sgl)) * 4 + 0];
            float d = yt - (me + yp);
            g_rowsq[(size_t)(b * HH + h) * SS + sgl] = d * d;
        }
        __syncwarp();
    }
}

// ---------------- passthrough copies ----------------
__global__ void copy_kernel(const float* __restrict__ y,
                            const float* __restrict__ yp,
                            const float* __restrict__ err,
                            float* __restrict__ out)
{
    int i = blockIdx.x * blockDim.x + threadIdx.x;
    if (i < 32768) out[OFF_Y + i] = y[i];
    else if (i < 65536) out[OFF_YPRED + (i - 32768)] = yp[i - 32768];
    else if (i < 73728) { int j = i - 65536; out[OFF_ERR + j] = err[(size_t)j * 4]; }
}

// ---------------- final scalar reduce ----------------
__global__ void reduce_kernel(float* __restrict__ out)
{
    __shared__ float sh[1024];
    float s = 0.f;
    for (int i = threadIdx.x; i < NROW; i += 1024) s += g_rowsq[i];
    sh[threadIdx.x] = s;
    __syncthreads();
    for (int o = 512; o; o >>= 1) {
        if (threadIdx.x < o) sh[threadIdx.x] += sh[threadIdx.x + o];
        __syncthreads();
    }
    if (threadIdx.x == 0) out[OFF_SCORE] = sh[0] * (1.f / (float)NROW);
}

// ---------------- launch ----------------
extern "C" void kernel_launch(void* const* d_in, const int* in_sizes, int n_in,
                              void* d_out, int out_size)
{
    const float* Xt   = (const float*)d_in[0];
    const float* Xs   = (const float*)d_in[1];
    const float* err  = (const float*)d_in[2];
    const float* y    = (const float*)d_in[3];
    const float* ypr  = (const float*)d_in[4];
    const float* W1   = (const float*)d_in[5];
    const float* b1   = (const float*)d_in[6];
    const float* W2   = (const float*)d_in[7];
    const float* b2   = (const float*)d_in[8];
    const float* W3   = (const float*)d_in[9];
    const float* b3   = (const float*)d_in[10];
    const float* W4   = (const float*)d_in[11];
    const float* b4   = (const float*)d_in[12];
    const float* Wq   = (const float*)d_in[13];
    const float* bq   = (const float*)d_in[14];
    const float* Wk   = (const float*)d_in[15];
    const float* bk   = (const float*)d_in[16];
    const float* gq   = (const float*)d_in[17];
    const float* betaq= (const float*)d_in[18];
    const float* gk   = (const float*)d_in[19];
    const float* betak= (const float*)d_in[20];
    float* out = (float*)d_out;

    float *p_h1, *p_h2, *p_ln, *p_qk;
    cudaGetSymbolAddress((void**)&p_h1, g_h1);
    cudaGetSymbolAddress((void**)&p_h2, g_h2);
    cudaGetSymbolAddress((void**)&p_ln, g_ln);
    cudaGetSymbolAddress((void**)&p_qk, g_qk);

    cudaFuncSetAttribute(sgemm_l4_ln,
                         cudaFuncAttributeMaxDynamicSharedMemorySize, 65536);
    cudaFuncSetAttribute(fused_scores_topk,
                         cudaFuncAttributeMaxDynamicSharedMemorySize, SM_FUSED_TOTAL);

    // 0: MLP layer 1 (dual source: true rows [0,8192), sim rows [8192,16384))
    sgemm_bias_dual<<<dim3(4, 128), 256>>>(Xt, Xs, INF_DIM, W1, HID, b1, p_h1, HID, HID, INF_DIM, 1);
    // 1,2: layers 2,3
    sgemm_bias<<<dim3(4, 128), 256>>>(p_h1, HID, W2, HID, b2, p_h2, HID, HID, HID, 1);
    sgemm_bias<<<dim3(4, 128), 256>>>(p_h2, HID, W3, HID, b3, p_h1, HID, HID, HID, 1);
    // 3: layer 4 + LayerNorm fused -> g_ln
    sgemm_l4_ln<<<128, 256, 65536>>>(p_h1, W4, b4, gq, betaq, gk, betak, p_ln);
    // 4: projections q/k + bf16 conversion fused
    sgemm_proj_cvt<<<dim3(4, 64, 2), 256>>>(p_ln, Wq, bq, Wk, bk, p_qk);
    // 5: fused scores MMA + register top-32 + exact fp32 rescore + quantiles
    fused_scores_topk<<<dim3(32, 16), 256, SM_FUSED_TOTAL>>>(p_qk, err, y, ypr, out);
    // 6: passthrough copies
    copy_kernel<<<288, 256>>>(y, ypr, err, out);
    // 7: scalar score
    reduce_kernel<<<1, 1024>>>(out);
}